// round 16
// baseline (speedup 1.0000x reference)
#include <cuda_runtime.h>
#include <cstdint>

// FirstFFTLinearLayer: 64-point forward complex DFT along dim 1 of
// [B=16, N=64, H=256, W=256] f32 (separate real/imag inputs).
// Output: REAL PART only, f32, [B, N, H, W]. (Established R1-R9.)
//
// R9 (1 thr/pix, 151 regs) = 121.3us @ 6.47 TB/s.
// R13 (2 thr/pix, 99 regs)  = 121.3us @ 6.40 TB/s.  -> not warp-limited.
// This round: quarter-split + float2. 4 threads per pixel (16 complex
// each; shfl_xor(2)=stage-64, shfl_xor(1)=stage-32, then register FFT-16),
// each thread carrying 2 adjacent pixels packed in float2. Same bytes per
// thread as R13 with HALF the memory instructions (LDG.64/STG.64, 8
// sectors per warp request) -> denser DRAM request stream.

#define HW 65536          // H*W
#define NFFT 64
#define BATCH 16
#define NPIX (BATCH * HW) // 1,048,576 pixels
#define TPB 128

__global__ __launch_bounds__(TPB)
void fft64_kernel(const float* __restrict__ re,
                  const float* __restrict__ im,
                  float* __restrict__ out) {
    __shared__ float2 tw[NFFT];
    {
        int t = threadIdx.x;
        if (t < NFFT) {
            float s, c;
            sincospif(-(float)t * (1.0f / 32.0f), &s, &c);  // e^{-2pi i t/64}
            tw[t] = make_float2(c, s);
        }
    }
    __syncthreads();

    const int gtid = blockIdx.x * TPB + threadIdx.x;
    const int q    = gtid & 3;          // quarter: j in [16q, 16q+16)
    const int pp   = gtid >> 2;         // pixel-pair index
    const int pix0 = pp << 1;           // even pixel (w even)
    int s_ = pix0 & (HW - 1);
    int b  = pix0 >> 16;
    const size_t base = (size_t)b * (NFFT * (size_t)HW) + (size_t)s_;

    // float2 views: .x = pixel0, .y = pixel1 (adjacent w). base is even.
    const float2* pr2 = (const float2*)(re + base);
    const float2* pi2 = (const float2*)(im + base);
    const int HW2 = HW / 2;

    // Front-batched loads: 32 independent LDG.64.
    float2 X[16], Y[16];                // re / im, 2 pixels wide
#pragma unroll
    for (int t = 0; t < 16; t++) X[t] = pr2[(size_t)(16 * q + t) * HW2];
#pragma unroll
    for (int t = 0; t < 16; t++) Y[t] = pi2[(size_t)(16 * q + t) * HW2];

    const unsigned FULL = 0xFFFFFFFFu;
    const int b64 = (q >> 1);   // stage-64 branch  -> k bit0
    const int b32 = (q & 1);    // stage-32 branch  -> k bit1

    // Stage m=64 across lanes q <-> q^2. u = j in [0,32), v = j+32.
#pragma unroll
    for (int t = 0; t < 16; t++) {
        float qxr = __shfl_xor_sync(FULL, X[t].x, 2);
        float qyr = __shfl_xor_sync(FULL, X[t].y, 2);
        float qxi = __shfl_xor_sync(FULL, Y[t].x, 2);
        float qyi = __shfl_xor_sync(FULL, Y[t].y, 2);
        // sum (branch 0) — symmetric
        float sxr = X[t].x + qxr, syr = X[t].y + qyr;
        float sxi = Y[t].x + qxi, syi = Y[t].y + qyi;
        // diff u-v: on b64=1 lanes X holds v, partner holds u -> Q - X
        float dxr = qxr - X[t].x, dyr = qyr - X[t].y;
        float dxi = qxi - Y[t].x, dyi = qyi - Y[t].y;
        float2 w = tw[16 * b32 + t];    // j in [0,32)
        float txr = dxr * w.x - dxi * w.y, tyr = dyr * w.x - dyi * w.y;
        float txi = dxr * w.y + dxi * w.x, tyi = dyr * w.y + dyi * w.x;
        X[t].x = b64 ? txr : sxr;  X[t].y = b64 ? tyr : syr;
        Y[t].x = b64 ? txi : sxi;  Y[t].y = b64 ? tyi : syi;
    }

    // Stage m=32 across lanes q <-> q^1. Stream index j32 = 16*b32 + t.
#pragma unroll
    for (int t = 0; t < 16; t++) {
        float qxr = __shfl_xor_sync(FULL, X[t].x, 1);
        float qyr = __shfl_xor_sync(FULL, X[t].y, 1);
        float qxi = __shfl_xor_sync(FULL, Y[t].x, 1);
        float qyi = __shfl_xor_sync(FULL, Y[t].y, 1);
        float sxr = X[t].x + qxr, syr = X[t].y + qyr;
        float sxi = Y[t].x + qxi, syi = Y[t].y + qyi;
        float dxr = qxr - X[t].x, dyr = qyr - X[t].y;
        float dxi = qxi - Y[t].x, dyi = qyi - Y[t].y;
        float2 w = tw[2 * t];           // W32^t = W64^{2t}
        float txr = dxr * w.x - dxi * w.y, tyr = dyr * w.x - dyi * w.y;
        float txi = dxr * w.y + dxi * w.x, tyi = dyr * w.y + dyi * w.x;
        X[t].x = b32 ? txr : sxr;  X[t].y = b32 ? tyr : syr;
        Y[t].x = b32 ? txi : sxi;  Y[t].y = b32 ? tyi : syi;
    }

    // In-register 16-point DIF FFT (stages m=16..2), twiddle W16^j = W64^{4j}.
#pragma unroll
    for (int m = 16; m >= 2; m >>= 1) {
        const int hm   = m >> 1;
        const int step = NFFT / m;
#pragma unroll
        for (int k = 0; k < 16; k += m) {
#pragma unroll
            for (int j = 0; j < hm; j++) {
                float2 ur = X[k + j],      ui = Y[k + j];
                float2 vr = X[k + j + hm], vi = Y[k + j + hm];
                X[k + j].x = ur.x + vr.x;  X[k + j].y = ur.y + vr.y;
                Y[k + j].x = ui.x + vi.x;  Y[k + j].y = ui.y + vi.y;
                float dxr = ur.x - vr.x, dyr = ur.y - vr.y;
                float dxi = ui.x - vi.x, dyi = ui.y - vi.y;
                float2 w = tw[(j * step) & (NFFT - 1)];
                X[k + j + hm].x = dxr * w.x - dxi * w.y;
                X[k + j + hm].y = dyr * w.x - dyi * w.y;
                Y[k + j + hm].x = dxr * w.y + dxi * w.x;
                Y[k + j + hm].y = dyr * w.y + dyi * w.x;
            }
        }
    }

    // Output bin k = 4r + 2*b32 + b64 ; slot p = brev4(r). Real part only,
    // stored as float2 (2 adjacent pixels).
    float2* po = (float2*)(out + base + (size_t)(2 * b32 + b64) * HW);
#pragma unroll
    for (int r = 0; r < 16; r++) {
        int p = (int)(__brev((unsigned)r) >> 28);  // 4-bit bit-reverse
        po[(size_t)(4 * r) * HW2] = X[p];
    }
}

extern "C" void kernel_launch(void* const* d_in, const int* in_sizes, int n_in,
                              void* d_out, int out_size) {
    // Weight = smallest input (unused); remaining two in d_in order = (re, im).
    int wmin = 0;
    for (int i = 1; i < n_in; i++)
        if (in_sizes[i] < in_sizes[wmin]) wmin = i;

    const float* adc_real = nullptr;
    const float* adc_imag = nullptr;
    for (int i = 0; i < n_in; i++) {
        if (i == wmin) continue;
        if (!adc_real)      adc_real = (const float*)d_in[i];
        else if (!adc_imag) adc_imag = (const float*)d_in[i];
    }
    if (!adc_real || !adc_imag) return;

    float* out = (float*)d_out;
    // 4 threads/pixel, 2 pixels/thread -> 2*NPIX threads.
    const int blocks = (2 * NPIX) / TPB;  // 16384
    fft64_kernel<<<blocks, TPB>>>(adc_real, adc_imag, out);
}